// round 15
// baseline (speedup 1.0000x reference)
#include <cuda_runtime.h>
#include <cfloat>

// Problem constants (reference: xyz [4, 8192, 3], K=16)
#define BB   4
#define NN   8192
#define NBZ  32                  // z slabs per batch
#define NBY  32                  // y bins per slab
#define NBT  (NBZ * NBY)         // 1024 sort bins
#define KK   16
#define TPB  256                 // 8 warps, 16 queries per block
#define FULL 0xffffffffu

// ---- device scratch (static: allocation-free) ----
__device__ float4 g_zpts[BB][NN];        // (z-slab, y-bin)-sorted points (x,y,z,|x|^2)
__device__ int    g_zidx[BB][NN];        // original indices, sorted
__device__ int    g_bst[BB][NBT + 1];    // bin start offsets
__device__ float  g_mm[BB][4];           // zmin, zmax, ymin, ymax (with margin)

__device__ __forceinline__ bool lex_less(float d, int i, float ed, int ei) {
    return (d < ed) || (d == ed && i < ei);
}

// Ascending lexicographic bitonic sort of 32 (d,i) pairs across the warp.
__device__ __forceinline__ void bitonic32(float& d, int& i, int lane) {
#pragma unroll
    for (int k = 2; k <= 32; k <<= 1) {
#pragma unroll
        for (int j = k >> 1; j > 0; j >>= 1) {
            const float od = __shfl_xor_sync(FULL, d, j);
            const int   oi = __shfl_xor_sync(FULL, i, j);
            const bool keep_min = ((lane & k) == 0) == ((lane & j) == 0);
            const bool less = lex_less(od, oi, d, i);
            if (keep_min == less) { d = od; i = oi; }
        }
    }
}

// Bin formulas — SAME everywhere (build + search).
__device__ __forceinline__ int binz(float z, float mn, float inv) {
    int c = (int)((z - mn) * inv);
    return min(NBZ - 1, max(0, c));
}
__device__ __forceinline__ int biny(float y, float mn, float inv) {
    int c = (int)((y - mn) * inv);
    return min(NBY - 1, max(0, c));
}

// ---- 1: fused build (minmax + count + scan + scatter), 1 block per batch ----
__global__ __launch_bounds__(1024)
void k_build(const float* __restrict__ xyz) {
    __shared__ int s_cnt[NBT];
    __shared__ int s_cur[NBT];
    __shared__ int s_ws[32];
    __shared__ float s_red[4][32];

    const int b = blockIdx.x;
    const int tid = threadIdx.x;
    const int lane = tid & 31, w = tid >> 5;
    const float* base = xyz + (size_t)b * NN * 3;

    // Load 8 points per thread (kept in registers for all phases)
    float px[8], py[8], pz[8];
    int   pi[8];
#pragma unroll
    for (int k = 0; k < 8; k++) {
        const int i = tid + k * 1024;
        pi[k] = i;
        px[k] = base[3 * i + 0];
        py[k] = base[3 * i + 1];
        pz[k] = base[3 * i + 2];
    }

    // Phase A: block min/max of z and y
    float mnz = FLT_MAX, mxz = -FLT_MAX, mny = FLT_MAX, mxy = -FLT_MAX;
#pragma unroll
    for (int k = 0; k < 8; k++) {
        mnz = fminf(mnz, pz[k]); mxz = fmaxf(mxz, pz[k]);
        mny = fminf(mny, py[k]); mxy = fmaxf(mxy, py[k]);
    }
#pragma unroll
    for (int o = 16; o; o >>= 1) {
        mnz = fminf(mnz, __shfl_xor_sync(FULL, mnz, o));
        mxz = fmaxf(mxz, __shfl_xor_sync(FULL, mxz, o));
        mny = fminf(mny, __shfl_xor_sync(FULL, mny, o));
        mxy = fmaxf(mxy, __shfl_xor_sync(FULL, mxy, o));
    }
    if (lane == 0) {
        s_red[0][w] = mnz; s_red[1][w] = mxz;
        s_red[2][w] = mny; s_red[3][w] = mxy;
    }
    // zero counters while reduction lands
    s_cnt[tid] = 0;
    __syncthreads();
    if (tid == 0) {
        float a = FLT_MAX, c = -FLT_MAX, d = FLT_MAX, e = -FLT_MAX;
#pragma unroll
        for (int i = 0; i < 32; i++) {
            a = fminf(a, s_red[0][i]); c = fmaxf(c, s_red[1][i]);
            d = fminf(d, s_red[2][i]); e = fmaxf(e, s_red[3][i]);
        }
        g_mm[b][0] = a - 1e-4f; g_mm[b][1] = c + 1e-4f;
        g_mm[b][2] = d - 1e-4f; g_mm[b][3] = e + 1e-4f;
        s_red[0][0] = a - 1e-4f; s_red[1][0] = c + 1e-4f;
        s_red[2][0] = d - 1e-4f; s_red[3][0] = e + 1e-4f;
    }
    __syncthreads();
    const float zmn = s_red[0][0], zmx = s_red[1][0];
    const float ymn = s_red[2][0], ymx = s_red[3][0];
    const float invz = NBZ / (zmx - zmn);
    const float invy = NBY / (ymx - ymn);

    // Phase B: count
    int bv[8];
#pragma unroll
    for (int k = 0; k < 8; k++) {
        bv[k] = binz(pz[k], zmn, invz) * NBY + biny(py[k], ymn, invy);
        atomicAdd(&s_cnt[bv[k]], 1);
    }
    __syncthreads();

    // Phase C: exclusive scan of 1024 bins
    const int c0 = s_cnt[tid];
    int s = c0;
#pragma unroll
    for (int o = 1; o < 32; o <<= 1) {
        const int v = __shfl_up_sync(FULL, s, o);
        if (lane >= o) s += v;
    }
    if (lane == 31) s_ws[w] = s;
    __syncthreads();
    if (w == 0) {
        int x = s_ws[lane];
        int e2 = x;
#pragma unroll
        for (int o = 1; o < 32; o <<= 1) {
            const int v = __shfl_up_sync(FULL, e2, o);
            if (lane >= o) e2 += v;
        }
        s_ws[lane] = e2 - x;
    }
    __syncthreads();
    const int excl = s - c0 + s_ws[w];
    g_bst[b][tid] = excl;
    s_cur[tid] = excl;
    if (tid == NBT - 1) g_bst[b][NBT] = excl + c0;   // == NN
    __syncthreads();

    // Phase D: scatter
#pragma unroll
    for (int k = 0; k < 8; k++) {
        const int pos = atomicAdd(&s_cur[bv[k]], 1);
        g_zpts[b][pos] = make_float4(px[k], py[k], pz[k],
                                     px[k] * px[k] + py[k] * py[k] + pz[k] * pz[k]);
        g_zidx[b][pos] = pi[k];
    }
}

// ---- 2: warp-per-2-queries slab walk with tau-adaptive y-windows ----
__global__ __launch_bounds__(TPB)
void k_search(const float* __restrict__ xyz, float* __restrict__ out, int out_size) {
    const int lane = threadIdx.x & 31;
    const int wid  = threadIdx.x >> 5;
    const int b  = blockIdx.x / (NN / 16);
    const int p  = (blockIdx.x % (NN / 16)) * 16 + wid * 2;   // sorted position
    const int t   = lane & 15;
    const int seg = lane >> 4;

    const float4* __restrict__ zp = g_zpts[b];
    const int*    __restrict__ zi = g_zidx[b];
    const int*    __restrict__ bst = g_bst[b];

    const float4 P0 = zp[p];
    const float4 P1 = zp[p + 1];
    const int qid0 = zi[p], qid1 = zi[p + 1];
    const float q0x = P0.x, q0y = P0.y, q0z = P0.z, sq0 = P0.w;
    const float q1x = P1.x, q1y = P1.y, q1z = P1.z, sq1 = P1.w;

    const float zmn = g_mm[b][0], zmx = g_mm[b][1];
    const float ymn = g_mm[b][2], ymx = g_mm[b][3];
    const float wz = (zmx - zmn) * (1.0f / NBZ);
    const float invz = NBZ / (zmx - zmn);
    const float invy = NBY / (ymx - ymn);
    const int h = binz(q0z, zmn, invz);

    float ld = FLT_MAX;
    int   li = 0x7fffffff;
    float tau0 = FLT_MAX, tau1 = FLT_MAX;
    bool warm = false;

#define ROUND(CC, CI)                                                           \
    {                                                                           \
        float dot0 = q0x * (CC).x;                                              \
        dot0 = fmaf(q0y, (CC).y, dot0);                                         \
        dot0 = fmaf(q0z, (CC).z, dot0);                                         \
        float dot1 = q1x * (CC).x;                                              \
        dot1 = fmaf(q1y, (CC).y, dot1);                                         \
        dot1 = fmaf(q1z, (CC).z, dot1);                                         \
        const float d2a = fmaf(-2.0f, dot0, sq0 + (CC).w);                      \
        const float d2b = fmaf(-2.0f, dot1, sq1 + (CC).w);                      \
        unsigned m0 = __ballot_sync(FULL, d2a < tau0);                          \
        unsigned m1 = __ballot_sync(FULL, d2b < tau1);                          \
        if (m0 | m1) {                                                          \
            const bool had0 = (m0 != 0), had1 = (m1 != 0);                      \
            while (m0) {                                                        \
                const int src = __ffs(m0) - 1;                                  \
                m0 &= m0 - 1;                                                   \
                const float dv = __shfl_sync(FULL, d2a, src);                   \
                const int   iv = __shfl_sync(FULL, (CI), src);                  \
                const float pd = __shfl_up_sync(FULL, ld, 1, 16);               \
                const int   pi2 = __shfl_up_sync(FULL, li, 1, 16);              \
                const bool ct = lex_less(dv, iv, ld, li);                       \
                const bool cp2 = (t > 0) && lex_less(dv, iv, pd, pi2);          \
                if (seg == 0 && ct) { ld = cp2 ? pd : dv; li = cp2 ? pi2 : iv; } \
            }                                                                   \
            while (m1) {                                                        \
                const int src = __ffs(m1) - 1;                                  \
                m1 &= m1 - 1;                                                   \
                const float dv = __shfl_sync(FULL, d2b, src);                   \
                const int   iv = __shfl_sync(FULL, (CI), src);                  \
                const float pd = __shfl_up_sync(FULL, ld, 1, 16);               \
                const int   pi2 = __shfl_up_sync(FULL, li, 1, 16);              \
                const bool ct = lex_less(dv, iv, ld, li);                       \
                const bool cp2 = (t > 0) && lex_less(dv, iv, pd, pi2);          \
                if (seg == 1 && ct) { ld = cp2 ? pd : dv; li = cp2 ? pi2 : iv; } \
            }                                                                   \
            if (had0) tau0 = __shfl_sync(FULL, ld, 15);                         \
            if (had1) tau1 = __shfl_sync(FULL, ld, 31);                         \
        }                                                                       \
    }

#define WARMUP(CC, CI)                                                          \
    {                                                                           \
        float dot0 = q0x * (CC).x;                                              \
        dot0 = fmaf(q0y, (CC).y, dot0);                                         \
        dot0 = fmaf(q0z, (CC).z, dot0);                                         \
        float dot1 = q1x * (CC).x;                                              \
        dot1 = fmaf(q1y, (CC).y, dot1);                                         \
        dot1 = fmaf(q1z, (CC).z, dot1);                                         \
        const float d2a = fmaf(-2.0f, dot0, sq0 + (CC).w);                      \
        const float d2b = fmaf(-2.0f, dot1, sq1 + (CC).w);                      \
        float da = d2a; int ia = (CI);                                          \
        bitonic32(da, ia, lane);                                                \
        float db = d2b; int ib = (CI);                                          \
        bitonic32(db, ib, lane);                                                \
        const float d1v = __shfl_sync(FULL, db, (lane - 16) & 31);              \
        const int   i1v = __shfl_sync(FULL, ib, (lane - 16) & 31);              \
        ld = seg ? d1v : da;                                                    \
        li = seg ? i1v : ia;                                                    \
        tau0 = __shfl_sync(FULL, ld, 15);                                       \
        tau1 = __shfl_sync(FULL, ld, 31);                                       \
    }

#define DORANGE(PS, PE)                                                         \
    {                                                                           \
        int p0 = (PS);                                                          \
        if (!warm && p0 < (PE)) {                                               \
            const int pp = p0 + lane;                                           \
            const bool ok = pp < (PE);                                          \
            const float4 cw = ok ? zp[pp] : make_float4(0.f, 0.f, 0.f, FLT_MAX); \
            const int   cwi = ok ? zi[pp] : 0x7fffffff;                         \
            WARMUP(cw, cwi);                                                    \
            warm = true;                                                        \
            p0 += 32;                                                           \
        }                                                                       \
        if (p0 < (PE)) {                                                        \
            int pp = p0 + lane;                                                 \
            bool ok = pp < (PE);                                                \
            float4 cc = ok ? zp[pp] : make_float4(0.f, 0.f, 0.f, FLT_MAX);      \
            int    ci = ok ? zi[pp] : 0x7fffffff;                               \
            for (; p0 < (PE); p0 += 32) {                                       \
                float4 nc = make_float4(0.f, 0.f, 0.f, FLT_MAX);                \
                int    ni = 0x7fffffff;                                         \
                if (p0 + 32 < (PE)) {                                           \
                    const int np2 = p0 + 32 + lane;                             \
                    const bool nok = np2 < (PE);                                \
                    if (nok) { nc = zp[np2]; ni = zi[np2]; }                    \
                }                                                               \
                ROUND(cc, ci);                                                  \
                cc = nc; ci = ni;                                               \
            }                                                                   \
        }                                                                       \
    }

    // Scan slab s restricted to the tau-certified y-window (union of both queries).
#define DOSLAB(S)                                                               \
    {                                                                           \
        int ylo, yhi;                                                           \
        if (tau0 < FLT_MAX && tau1 < FLT_MAX) {                                 \
            const float r0 = sqrtf(tau0) * 1.001f;                              \
            const float r1 = sqrtf(tau1) * 1.001f;                              \
            ylo = min(biny(q0y - r0, ymn, invy), biny(q1y - r1, ymn, invy));    \
            yhi = max(biny(q0y + r0, ymn, invy), biny(q1y + r1, ymn, invy));    \
        } else { ylo = 0; yhi = NBY - 1; }                                      \
        const int ps = bst[(S) * NBY + ylo];                                    \
        const int pe = bst[(S) * NBY + yhi + 1];                                \
        DORANGE(ps, pe);                                                        \
    }

    int lo = h, hi = h;
    DORANGE(bst[h * NBY], bst[h * NBY + NBY]);   // home slab: full

    for (;;) {
        float bd0 = FLT_MAX, bd1 = FLT_MAX;
        if (lo > 0) {
            const float e = zmn + lo * wz;
            bd0 = fminf(bd0, q0z - e);
            bd1 = fminf(bd1, q1z - e);
        }
        if (hi < NBZ - 1) {
            const float e = zmn + (hi + 1) * wz;
            bd0 = fminf(bd0, e - q0z);
            bd1 = fminf(bd1, e - q1z);
        }
        const bool cov = (lo == 0) && (hi == NBZ - 1);
        const bool d0 = (tau0 < FLT_MAX) && (bd0 > 0.0f) && (tau0 <= 0.98f * bd0 * bd0);
        const bool d1 = (tau1 < FLT_MAX) && (bd1 > 0.0f) && (tau1 <= 0.98f * bd1 * bd1);
        if (cov || (d0 && d1)) break;

        bool up;
        if (lo == 0) up = true;
        else if (hi == NBZ - 1) up = false;
        else {
            const float zm = 0.5f * (q0z + q1z);
            const float du = (zmn + (hi + 1) * wz) - zm;
            const float dd = zm - (zmn + lo * wz);
            up = du <= dd;
        }
        if (up) { hi++; DOSLAB(hi); }
        else    { lo--; DOSLAB(lo); }
    }
#undef ROUND
#undef WARMUP
#undef DORANGE
#undef DOSLAB

    // ---- Epilogue: features [B,N,K,10] then indices [B,N,K] as float ----
    const float* __restrict__ bx = xyz + (size_t)b * NN * 3;
    const size_t feat_total = (size_t)BB * NN * KK * 10;
    const bool write_idx = ((size_t)out_size >= feat_total + (size_t)BB * NN * KK);
    {
        const int   q  = seg ? qid1 : qid0;
        const float qx = seg ? q1x : q0x;
        const float qy = seg ? q1y : q0y;
        const float qz = seg ? q1z : q0z;
        const size_t qlin = (size_t)b * NN + q;
        const int j = li;
        const float nx = bx[3 * j + 0];
        const float ny = bx[3 * j + 1];
        const float nz = bx[3 * j + 2];

        float* o = out + qlin * KK * 10 + (size_t)t * 10;
        o[0] = ld;
        o[1] = qx - nx;
        o[2] = qy - ny;
        o[3] = qz - nz;
        o[4] = qx;
        o[5] = qy;
        o[6] = qz;
        o[7] = nx;
        o[8] = ny;
        o[9] = nz;
        if (write_idx) out[feat_total + qlin * KK + t] = (float)j;
    }
}

extern "C" void kernel_launch(void* const* d_in, const int* in_sizes, int n_in,
                              void* d_out, int out_size) {
    const float* xyz = (const float*)d_in[0];
    float* out = (float*)d_out;

    k_build<<<BB, 1024>>>(xyz);                        // launch 1
    k_search<<<BB * (NN / 16), TPB>>>(xyz, out, out_size);  // launch 2
}

// round 16
// speedup vs baseline: 1.5479x; 1.5479x over previous
#include <cuda_runtime.h>
#include <cfloat>

// Problem constants (reference: xyz [4, 8192, 3], K=16)
#define BB   4
#define NN   8192
#define NBZ  32                  // z slabs per batch
#define NBY  32                  // y bins per slab
#define NBT  (NBZ * NBY)         // 1024 sort bins
#define KK   16
#define TPB  256                 // 8 warps, 16 queries per block
#define FULL 0xffffffffu

// ---- device scratch (static: allocation-free) ----
__device__ float4 g_zpts[BB][NN];        // (z-slab, y-bin)-sorted points (x,y,z,|x|^2)
__device__ int    g_zidx[BB][NN];        // original indices, sorted
__device__ int    g_bst[BB][NBT + 1];    // bin start offsets
__device__ float  g_mm[BB][4];           // zmin, zmax, ymin, ymax (with margin)

__device__ __forceinline__ bool lex_less(float d, int i, float ed, int ei) {
    return (d < ed) || (d == ed && i < ei);
}

// Ascending lexicographic bitonic sort of 32 (d,i) pairs across the warp.
__device__ __forceinline__ void bitonic32(float& d, int& i, int lane) {
#pragma unroll
    for (int k = 2; k <= 32; k <<= 1) {
#pragma unroll
        for (int j = k >> 1; j > 0; j >>= 1) {
            const float od = __shfl_xor_sync(FULL, d, j);
            const int   oi = __shfl_xor_sync(FULL, i, j);
            const bool keep_min = ((lane & k) == 0) == ((lane & j) == 0);
            const bool less = lex_less(od, oi, d, i);
            if (keep_min == less) { d = od; i = oi; }
        }
    }
}

// Bin formulas — SAME everywhere (build + search).
__device__ __forceinline__ int binz(float z, float mn, float inv) {
    int c = (int)((z - mn) * inv);
    return min(NBZ - 1, max(0, c));
}
__device__ __forceinline__ int biny(float y, float mn, float inv) {
    int c = (int)((y - mn) * inv);
    return min(NBY - 1, max(0, c));
}

// ---- 1: fused build (minmax + count + scan + scatter), 1 block per batch ----
__global__ __launch_bounds__(1024)
void k_build(const float* __restrict__ xyz) {
    __shared__ int s_cnt[NBT];
    __shared__ int s_cur[NBT];
    __shared__ int s_ws[32];
    __shared__ float s_red[4][32];

    const int b = blockIdx.x;
    const int tid = threadIdx.x;
    const int lane = tid & 31, w = tid >> 5;
    const float* base = xyz + (size_t)b * NN * 3;

    float px[8], py[8], pz[8];
    int   pi[8];
#pragma unroll
    for (int k = 0; k < 8; k++) {
        const int i = tid + k * 1024;
        pi[k] = i;
        px[k] = base[3 * i + 0];
        py[k] = base[3 * i + 1];
        pz[k] = base[3 * i + 2];
    }

    float mnz = FLT_MAX, mxz = -FLT_MAX, mny = FLT_MAX, mxy = -FLT_MAX;
#pragma unroll
    for (int k = 0; k < 8; k++) {
        mnz = fminf(mnz, pz[k]); mxz = fmaxf(mxz, pz[k]);
        mny = fminf(mny, py[k]); mxy = fmaxf(mxy, py[k]);
    }
#pragma unroll
    for (int o = 16; o; o >>= 1) {
        mnz = fminf(mnz, __shfl_xor_sync(FULL, mnz, o));
        mxz = fmaxf(mxz, __shfl_xor_sync(FULL, mxz, o));
        mny = fminf(mny, __shfl_xor_sync(FULL, mny, o));
        mxy = fmaxf(mxy, __shfl_xor_sync(FULL, mxy, o));
    }
    if (lane == 0) {
        s_red[0][w] = mnz; s_red[1][w] = mxz;
        s_red[2][w] = mny; s_red[3][w] = mxy;
    }
    s_cnt[tid] = 0;
    __syncthreads();
    if (tid == 0) {
        float a = FLT_MAX, c = -FLT_MAX, d = FLT_MAX, e = -FLT_MAX;
#pragma unroll
        for (int i = 0; i < 32; i++) {
            a = fminf(a, s_red[0][i]); c = fmaxf(c, s_red[1][i]);
            d = fminf(d, s_red[2][i]); e = fmaxf(e, s_red[3][i]);
        }
        g_mm[b][0] = a - 1e-4f; g_mm[b][1] = c + 1e-4f;
        g_mm[b][2] = d - 1e-4f; g_mm[b][3] = e + 1e-4f;
        s_red[0][0] = a - 1e-4f; s_red[1][0] = c + 1e-4f;
        s_red[2][0] = d - 1e-4f; s_red[3][0] = e + 1e-4f;
    }
    __syncthreads();
    const float zmn = s_red[0][0], zmx = s_red[1][0];
    const float ymn = s_red[2][0], ymx = s_red[3][0];
    const float invz = NBZ / (zmx - zmn);
    const float invy = NBY / (ymx - ymn);

    int bv[8];
#pragma unroll
    for (int k = 0; k < 8; k++) {
        bv[k] = binz(pz[k], zmn, invz) * NBY + biny(py[k], ymn, invy);
        atomicAdd(&s_cnt[bv[k]], 1);
    }
    __syncthreads();

    const int c0 = s_cnt[tid];
    int s = c0;
#pragma unroll
    for (int o = 1; o < 32; o <<= 1) {
        const int v = __shfl_up_sync(FULL, s, o);
        if (lane >= o) s += v;
    }
    if (lane == 31) s_ws[w] = s;
    __syncthreads();
    if (w == 0) {
        int x = s_ws[lane];
        int e2 = x;
#pragma unroll
        for (int o = 1; o < 32; o <<= 1) {
            const int v = __shfl_up_sync(FULL, e2, o);
            if (lane >= o) e2 += v;
        }
        s_ws[lane] = e2 - x;
    }
    __syncthreads();
    const int excl = s - c0 + s_ws[w];
    g_bst[b][tid] = excl;
    s_cur[tid] = excl;
    if (tid == NBT - 1) g_bst[b][NBT] = excl + c0;   // == NN
    __syncthreads();

#pragma unroll
    for (int k = 0; k < 8; k++) {
        const int pos = atomicAdd(&s_cur[bv[k]], 1);
        g_zpts[b][pos] = make_float4(px[k], py[k], pz[k],
                                     px[k] * px[k] + py[k] * py[k] + pz[k] * pz[k]);
        g_zidx[b][pos] = pi[k];
    }
}

// ---- 2: warp-per-2-queries, tau-seeded slab walk with y-windows ----
__global__ __launch_bounds__(TPB)
void k_search(const float* __restrict__ xyz, float* __restrict__ out, int out_size) {
    const int lane = threadIdx.x & 31;
    const int wid  = threadIdx.x >> 5;
    const int b  = blockIdx.x / (NN / 16);
    const int p  = (blockIdx.x % (NN / 16)) * 16 + wid * 2;   // sorted position
    const int t   = lane & 15;
    const int seg = lane >> 4;

    const float4* __restrict__ zp = g_zpts[b];
    const int*    __restrict__ zi = g_zidx[b];
    const int*    __restrict__ bst = g_bst[b];

    const float4 P0 = zp[p];
    const float4 P1 = zp[p + 1];
    const int qid0 = zi[p], qid1 = zi[p + 1];
    const float q0x = P0.x, q0y = P0.y, q0z = P0.z, sq0 = P0.w;
    const float q1x = P1.x, q1y = P1.y, q1z = P1.z, sq1 = P1.w;

    const float zmn = g_mm[b][0], zmx = g_mm[b][1];
    const float ymn = g_mm[b][2], ymx = g_mm[b][3];
    const float wz = (zmx - zmn) * (1.0f / NBZ);
    const float invz = NBZ / (zmx - zmn);
    const float invy = NBY / (ymx - ymn);
    const int h  = binz(q0z, zmn, invz);
    const int yb = biny(q0y, ymn, invy);

    float ld = FLT_MAX;
    int   li = 0x7fffffff;
    float tau0 = FLT_MAX, tau1 = FLT_MAX;
    bool warm = false;

#define ROUND(CC, CI)                                                           \
    {                                                                           \
        float dot0 = q0x * (CC).x;                                              \
        dot0 = fmaf(q0y, (CC).y, dot0);                                         \
        dot0 = fmaf(q0z, (CC).z, dot0);                                         \
        float dot1 = q1x * (CC).x;                                              \
        dot1 = fmaf(q1y, (CC).y, dot1);                                         \
        dot1 = fmaf(q1z, (CC).z, dot1);                                         \
        const float d2a = fmaf(-2.0f, dot0, sq0 + (CC).w);                      \
        const float d2b = fmaf(-2.0f, dot1, sq1 + (CC).w);                      \
        unsigned m0 = __ballot_sync(FULL, d2a < tau0);                          \
        unsigned m1 = __ballot_sync(FULL, d2b < tau1);                          \
        if (m0 | m1) {                                                          \
            const bool had0 = (m0 != 0), had1 = (m1 != 0);                      \
            while (m0) {                                                        \
                const int src = __ffs(m0) - 1;                                  \
                m0 &= m0 - 1;                                                   \
                const float dv = __shfl_sync(FULL, d2a, src);                   \
                const int   iv = __shfl_sync(FULL, (CI), src);                  \
                const float pd = __shfl_up_sync(FULL, ld, 1, 16);               \
                const int   pi2 = __shfl_up_sync(FULL, li, 1, 16);              \
                const bool ct = lex_less(dv, iv, ld, li);                       \
                const bool cp2 = (t > 0) && lex_less(dv, iv, pd, pi2);          \
                if (seg == 0 && ct) { ld = cp2 ? pd : dv; li = cp2 ? pi2 : iv; } \
            }                                                                   \
            while (m1) {                                                        \
                const int src = __ffs(m1) - 1;                                  \
                m1 &= m1 - 1;                                                   \
                const float dv = __shfl_sync(FULL, d2b, src);                   \
                const int   iv = __shfl_sync(FULL, (CI), src);                  \
                const float pd = __shfl_up_sync(FULL, ld, 1, 16);               \
                const int   pi2 = __shfl_up_sync(FULL, li, 1, 16);              \
                const bool ct = lex_less(dv, iv, ld, li);                       \
                const bool cp2 = (t > 0) && lex_less(dv, iv, pd, pi2);          \
                if (seg == 1 && ct) { ld = cp2 ? pd : dv; li = cp2 ? pi2 : iv; } \
            }                                                                   \
            if (had0) tau0 = __shfl_sync(FULL, ld, 15);                         \
            if (had1) tau1 = __shfl_sync(FULL, ld, 31);                         \
        }                                                                       \
    }

#define WARMUP(CC, CI)                                                          \
    {                                                                           \
        float dot0 = q0x * (CC).x;                                              \
        dot0 = fmaf(q0y, (CC).y, dot0);                                         \
        dot0 = fmaf(q0z, (CC).z, dot0);                                         \
        float dot1 = q1x * (CC).x;                                              \
        dot1 = fmaf(q1y, (CC).y, dot1);                                         \
        dot1 = fmaf(q1z, (CC).z, dot1);                                         \
        const float d2a = fmaf(-2.0f, dot0, sq0 + (CC).w);                      \
        const float d2b = fmaf(-2.0f, dot1, sq1 + (CC).w);                      \
        float da = d2a; int ia = (CI);                                          \
        bitonic32(da, ia, lane);                                                \
        float db = d2b; int ib = (CI);                                          \
        bitonic32(db, ib, lane);                                                \
        const float d1v = __shfl_sync(FULL, db, (lane - 16) & 31);              \
        const int   i1v = __shfl_sync(FULL, ib, (lane - 16) & 31);              \
        ld = seg ? d1v : da;                                                    \
        li = seg ? i1v : ia;                                                    \
        tau0 = __shfl_sync(FULL, ld, 15);                                       \
        tau1 = __shfl_sync(FULL, ld, 31);                                       \
    }

#define DORANGE(PS, PE)                                                         \
    {                                                                           \
        int p0 = (PS);                                                          \
        if (!warm && p0 < (PE)) {                                               \
            const int pp = p0 + lane;                                           \
            const bool ok = pp < (PE);                                          \
            const float4 cw = ok ? zp[pp] : make_float4(0.f, 0.f, 0.f, FLT_MAX); \
            const int   cwi = ok ? zi[pp] : 0x7fffffff;                         \
            WARMUP(cw, cwi);                                                    \
            warm = true;                                                        \
            p0 += 32;                                                           \
        }                                                                       \
        if (p0 < (PE)) {                                                        \
            int pp = p0 + lane;                                                 \
            bool ok = pp < (PE);                                                \
            float4 cc = ok ? zp[pp] : make_float4(0.f, 0.f, 0.f, FLT_MAX);      \
            int    ci = ok ? zi[pp] : 0x7fffffff;                               \
            for (; p0 < (PE); p0 += 32) {                                       \
                float4 nc = make_float4(0.f, 0.f, 0.f, FLT_MAX);                \
                int    ni = 0x7fffffff;                                         \
                if (p0 + 32 < (PE)) {                                           \
                    const int np2 = p0 + 32 + lane;                             \
                    const bool nok = np2 < (PE);                                \
                    if (nok) { nc = zp[np2]; ni = zi[np2]; }                    \
                }                                                               \
                ROUND(cc, ci);                                                  \
                cc = nc; ci = ni;                                               \
            }                                                                   \
        }                                                                       \
    }

    // Current tau-certified y-bin window (union over both queries).
#define YWIN(YLO, YHI)                                                          \
    {                                                                           \
        if (warm && tau0 < FLT_MAX && tau1 < FLT_MAX) {                         \
            const float r0 = sqrtf(tau0) * 1.001f;                              \
            const float r1 = sqrtf(tau1) * 1.001f;                              \
            (YLO) = min(biny(q0y - r0, ymn, invy), biny(q1y - r1, ymn, invy));  \
            (YHI) = max(biny(q0y + r0, ymn, invy), biny(q1y + r1, ymn, invy));  \
        } else { (YLO) = 0; (YHI) = NBY - 1; }                                  \
    }

    // ---- Seed: bins [yb-2, yb+2] of the home slab (closest candidates first) ----
    const int sl = max(0, yb - 2), sh = min(NBY - 1, yb + 2);
    DORANGE(bst[h * NBY + sl], bst[h * NBY + sh + 1]);

    // ---- Home-slab remainder under the seeded window ----
    {
        int ylo, yhi;
        YWIN(ylo, yhi);
        if (ylo < sl) DORANGE(bst[h * NBY + ylo], bst[h * NBY + sl]);
        if (yhi > sh) DORANGE(bst[h * NBY + sh + 1], bst[h * NBY + yhi + 1]);
    }

    // ---- Outward slab walk with per-slab y-windows ----
    int lo = h, hi = h;
    for (;;) {
        float bd0 = FLT_MAX, bd1 = FLT_MAX;
        if (lo > 0) {
            const float e = zmn + lo * wz;
            bd0 = fminf(bd0, q0z - e);
            bd1 = fminf(bd1, q1z - e);
        }
        if (hi < NBZ - 1) {
            const float e = zmn + (hi + 1) * wz;
            bd0 = fminf(bd0, e - q0z);
            bd1 = fminf(bd1, e - q1z);
        }
        const bool cov = (lo == 0) && (hi == NBZ - 1);
        const bool d0 = (tau0 < FLT_MAX) && (bd0 > 0.0f) && (tau0 <= 0.98f * bd0 * bd0);
        const bool d1 = (tau1 < FLT_MAX) && (bd1 > 0.0f) && (tau1 <= 0.98f * bd1 * bd1);
        if (cov || (d0 && d1)) break;

        bool up;
        if (lo == 0) up = true;
        else if (hi == NBZ - 1) up = false;
        else {
            const float zm = 0.5f * (q0z + q1z);
            const float du = (zmn + (hi + 1) * wz) - zm;
            const float dd = zm - (zmn + lo * wz);
            up = du <= dd;
        }
        int s2 = up ? ++hi : --lo;
        int ylo, yhi;
        YWIN(ylo, yhi);
        DORANGE(bst[s2 * NBY + ylo], bst[s2 * NBY + yhi + 1]);
    }
#undef ROUND
#undef WARMUP
#undef DORANGE
#undef YWIN

    // ---- Epilogue: features [B,N,K,10] then indices [B,N,K] as float ----
    const float* __restrict__ bx = xyz + (size_t)b * NN * 3;
    const size_t feat_total = (size_t)BB * NN * KK * 10;
    const bool write_idx = ((size_t)out_size >= feat_total + (size_t)BB * NN * KK);
    {
        const int   q  = seg ? qid1 : qid0;
        const float qx = seg ? q1x : q0x;
        const float qy = seg ? q1y : q0y;
        const float qz = seg ? q1z : q0z;
        const size_t qlin = (size_t)b * NN + q;
        const int j = li;
        const float nx = bx[3 * j + 0];
        const float ny = bx[3 * j + 1];
        const float nz = bx[3 * j + 2];

        float* o = out + qlin * KK * 10 + (size_t)t * 10;
        o[0] = ld;
        o[1] = qx - nx;
        o[2] = qy - ny;
        o[3] = qz - nz;
        o[4] = qx;
        o[5] = qy;
        o[6] = qz;
        o[7] = nx;
        o[8] = ny;
        o[9] = nz;
        if (write_idx) out[feat_total + qlin * KK + t] = (float)j;
    }
}

extern "C" void kernel_launch(void* const* d_in, const int* in_sizes, int n_in,
                              void* d_out, int out_size) {
    const float* xyz = (const float*)d_in[0];
    float* out = (float*)d_out;

    k_build<<<BB, 1024>>>(xyz);                              // launch 1
    k_search<<<BB * (NN / 16), TPB>>>(xyz, out, out_size);   // launch 2
}

// round 17
// speedup vs baseline: 1.9625x; 1.2678x over previous
#include <cuda_runtime.h>
#include <cfloat>

// Problem constants (reference: xyz [4, 8192, 3], K=16)
#define BB   4
#define NN   8192
#define NBZ  32                  // z slabs per batch
#define NBY  32                  // y bins per slab
#define NBT  (NBZ * NBY)         // 1024 sort bins
#define KK   16
#define TPB  256                 // 8 warps, 16 queries per block
#define BPB  (NN / 16)           // 512 blocks per batch
#define MTHR 10                  // merge-insert threshold (ballot popcount)
#define FULL 0xffffffffu

// ---- device scratch (static: allocation-free) ----
__device__ float4 g_zpts[BB][NN];        // (z-slab, y-bin)-sorted points (x,y,z,|x|^2)
__device__ int    g_zidx[BB][NN];        // original indices, sorted
__device__ int    g_bst[BB][NBT + 1];    // bin start offsets
__device__ float  g_mm[BB][4];           // zmin, zmax, ymin, ymax (with margin)

__device__ __forceinline__ bool lex_less(float d, int i, float ed, int ei) {
    return (d < ed) || (d == ed && i < ei);
}

// Ascending lexicographic bitonic sort of 32 (d,i) pairs across the warp.
__device__ __forceinline__ void bitonic32(float& d, int& i, int lane) {
#pragma unroll
    for (int k = 2; k <= 32; k <<= 1) {
#pragma unroll
        for (int j = k >> 1; j > 0; j >>= 1) {
            const float od = __shfl_xor_sync(FULL, d, j);
            const int   oi = __shfl_xor_sync(FULL, i, j);
            const bool keep_min = ((lane & k) == 0) == ((lane & j) == 0);
            const bool less = lex_less(od, oi, d, i);
            if (keep_min == less) { d = od; i = oi; }
        }
    }
}

// Batched insert: merge all 32 candidates (d2, ci) into query qseg's sorted
// 16-list (held in lanes qseg*16..qseg*16+15 of ld/li). Produces the lex-
// smallest 16 of (list ∪ candidates) — identical to serial insertion.
// Warp-uniform call required.
__device__ __forceinline__ void merge16(float d2, int ci, float& ld, int& li,
                                        int lane, int qseg) {
    float cd = d2; int cx = ci;
    bitonic32(cd, cx, lane);                       // candidates ascending
    // This query's list into lanes 0-15; best-16 candidates reversed into 16-31.
    const float av = __shfl_sync(FULL, ld, (lane + (qseg << 4)) & 31);
    const int   ai = __shfl_sync(FULL, li, (lane + (qseg << 4)) & 31);
    const float bv = __shfl_sync(FULL, cd, 31 - lane);
    const int   bi = __shfl_sync(FULL, cx, 31 - lane);
    float v  = (lane < 16) ? av : bv;
    int   vi = (lane < 16) ? ai : bi;
    // Bitonic merge (ascending): asc(16) ++ desc(16) is bitonic.
#pragma unroll
    for (int j = 16; j; j >>= 1) {
        const float ov = __shfl_xor_sync(FULL, v, j);
        const int   oi = __shfl_xor_sync(FULL, vi, j);
        const bool lower = (lane & j) == 0;
        const bool less = lex_less(ov, oi, v, vi);
        if (lower == less) { v = ov; vi = oi; }
    }
    // Merged rank t lives in lane t; write back to owning half.
    const float rv = __shfl_sync(FULL, v, lane & 15);
    const int   ri = __shfl_sync(FULL, vi, lane & 15);
    if ((lane >> 4) == qseg) { ld = rv; li = ri; }
}

// Bin formulas — SAME everywhere (build + search).
__device__ __forceinline__ int binz(float z, float mn, float inv) {
    int c = (int)((z - mn) * inv);
    return min(NBZ - 1, max(0, c));
}
__device__ __forceinline__ int biny(float y, float mn, float inv) {
    int c = (int)((y - mn) * inv);
    return min(NBY - 1, max(0, c));
}

// ---- 1: fused build (minmax + count + scan + scatter), 1 block per batch ----
__global__ __launch_bounds__(1024)
void k_build(const float* __restrict__ xyz) {
    __shared__ int s_cnt[NBT];
    __shared__ int s_cur[NBT];
    __shared__ int s_ws[32];
    __shared__ float s_red[4][32];

    const int b = blockIdx.x;
    const int tid = threadIdx.x;
    const int lane = tid & 31, w = tid >> 5;
    const float* base = xyz + (size_t)b * NN * 3;

    float px[8], py[8], pz[8];
    int   pi[8];
#pragma unroll
    for (int k = 0; k < 8; k++) {
        const int i = tid + k * 1024;
        pi[k] = i;
        px[k] = base[3 * i + 0];
        py[k] = base[3 * i + 1];
        pz[k] = base[3 * i + 2];
    }

    float mnz = FLT_MAX, mxz = -FLT_MAX, mny = FLT_MAX, mxy = -FLT_MAX;
#pragma unroll
    for (int k = 0; k < 8; k++) {
        mnz = fminf(mnz, pz[k]); mxz = fmaxf(mxz, pz[k]);
        mny = fminf(mny, py[k]); mxy = fmaxf(mxy, py[k]);
    }
#pragma unroll
    for (int o = 16; o; o >>= 1) {
        mnz = fminf(mnz, __shfl_xor_sync(FULL, mnz, o));
        mxz = fmaxf(mxz, __shfl_xor_sync(FULL, mxz, o));
        mny = fminf(mny, __shfl_xor_sync(FULL, mny, o));
        mxy = fmaxf(mxy, __shfl_xor_sync(FULL, mxy, o));
    }
    if (lane == 0) {
        s_red[0][w] = mnz; s_red[1][w] = mxz;
        s_red[2][w] = mny; s_red[3][w] = mxy;
    }
    s_cnt[tid] = 0;
    __syncthreads();
    if (tid == 0) {
        float a = FLT_MAX, c = -FLT_MAX, d = FLT_MAX, e = -FLT_MAX;
#pragma unroll
        for (int i = 0; i < 32; i++) {
            a = fminf(a, s_red[0][i]); c = fmaxf(c, s_red[1][i]);
            d = fminf(d, s_red[2][i]); e = fmaxf(e, s_red[3][i]);
        }
        g_mm[b][0] = a - 1e-4f; g_mm[b][1] = c + 1e-4f;
        g_mm[b][2] = d - 1e-4f; g_mm[b][3] = e + 1e-4f;
        s_red[0][0] = a - 1e-4f; s_red[1][0] = c + 1e-4f;
        s_red[2][0] = d - 1e-4f; s_red[3][0] = e + 1e-4f;
    }
    __syncthreads();
    const float zmn = s_red[0][0], zmx = s_red[1][0];
    const float ymn = s_red[2][0], ymx = s_red[3][0];
    const float invz = NBZ / (zmx - zmn);
    const float invy = NBY / (ymx - ymn);

    int bv[8];
#pragma unroll
    for (int k = 0; k < 8; k++) {
        bv[k] = binz(pz[k], zmn, invz) * NBY + biny(py[k], ymn, invy);
        atomicAdd(&s_cnt[bv[k]], 1);
    }
    __syncthreads();

    const int c0 = s_cnt[tid];
    int s = c0;
#pragma unroll
    for (int o = 1; o < 32; o <<= 1) {
        const int v = __shfl_up_sync(FULL, s, o);
        if (lane >= o) s += v;
    }
    if (lane == 31) s_ws[w] = s;
    __syncthreads();
    if (w == 0) {
        int x = s_ws[lane];
        int e2 = x;
#pragma unroll
        for (int o = 1; o < 32; o <<= 1) {
            const int v = __shfl_up_sync(FULL, e2, o);
            if (lane >= o) e2 += v;
        }
        s_ws[lane] = e2 - x;
    }
    __syncthreads();
    const int excl = s - c0 + s_ws[w];
    g_bst[b][tid] = excl;
    s_cur[tid] = excl;
    if (tid == NBT - 1) g_bst[b][NBT] = excl + c0;   // == NN
    __syncthreads();

#pragma unroll
    for (int k = 0; k < 8; k++) {
        const int pos = atomicAdd(&s_cur[bv[k]], 1);
        g_zpts[b][pos] = make_float4(px[k], py[k], pz[k],
                                     px[k] * px[k] + py[k] * py[k] + pz[k] * pz[k]);
        g_zidx[b][pos] = pi[k];
    }
}

// ---- 2: warp-per-2-queries, tau-seeded slab walk; warp-strided pairs ----
__global__ __launch_bounds__(TPB)
void k_search(const float* __restrict__ xyz, float* __restrict__ out, int out_size) {
    const int lane = threadIdx.x & 31;
    const int wid  = threadIdx.x >> 5;
    const int b   = blockIdx.x / BPB;
    const int blk = blockIdx.x - b * BPB;
    // Warp-strided assignment: block's warps sample pairs across the whole
    // sorted order -> uniform per-block work (kills block-duration tail).
    const int p = 2 * (blk + wid * BPB);          // sorted position of query 0
    const int t   = lane & 15;
    const int seg = lane >> 4;

    const float4* __restrict__ zp = g_zpts[b];
    const int*    __restrict__ zi = g_zidx[b];
    const int*    __restrict__ bst = g_bst[b];

    const float4 P0 = zp[p];
    const float4 P1 = zp[p + 1];
    const int qid0 = zi[p], qid1 = zi[p + 1];
    const float q0x = P0.x, q0y = P0.y, q0z = P0.z, sq0 = P0.w;
    const float q1x = P1.x, q1y = P1.y, q1z = P1.z, sq1 = P1.w;

    const float zmn = g_mm[b][0], zmx = g_mm[b][1];
    const float ymn = g_mm[b][2], ymx = g_mm[b][3];
    const float wz = (zmx - zmn) * (1.0f / NBZ);
    const float invz = NBZ / (zmx - zmn);
    const float invy = NBY / (ymx - ymn);
    const int h  = binz(q0z, zmn, invz);
    const int yb = biny(q0y, ymn, invy);

    float ld = FLT_MAX;
    int   li = 0x7fffffff;
    float tau0 = FLT_MAX, tau1 = FLT_MAX;
    bool warm = false;

#define ROUND(CC, CI)                                                           \
    {                                                                           \
        float dot0 = q0x * (CC).x;                                              \
        dot0 = fmaf(q0y, (CC).y, dot0);                                         \
        dot0 = fmaf(q0z, (CC).z, dot0);                                         \
        float dot1 = q1x * (CC).x;                                              \
        dot1 = fmaf(q1y, (CC).y, dot1);                                         \
        dot1 = fmaf(q1z, (CC).z, dot1);                                         \
        const float d2a = fmaf(-2.0f, dot0, sq0 + (CC).w);                      \
        const float d2b = fmaf(-2.0f, dot1, sq1 + (CC).w);                      \
        unsigned m0 = __ballot_sync(FULL, d2a < tau0);                          \
        unsigned m1 = __ballot_sync(FULL, d2b < tau1);                          \
        if (m0 | m1) {                                                          \
            const bool had0 = (m0 != 0), had1 = (m1 != 0);                      \
            if (__popc(m0) >= MTHR) {                                           \
                merge16(d2a, (CI), ld, li, lane, 0);                            \
            } else {                                                            \
                while (m0) {                                                    \
                    const int src = __ffs(m0) - 1;                              \
                    m0 &= m0 - 1;                                               \
                    const float dv = __shfl_sync(FULL, d2a, src);               \
                    const int   iv = __shfl_sync(FULL, (CI), src);              \
                    const float pd = __shfl_up_sync(FULL, ld, 1, 16);           \
                    const int   pi2 = __shfl_up_sync(FULL, li, 1, 16);          \
                    const bool ct = lex_less(dv, iv, ld, li);                   \
                    const bool cp2 = (t > 0) && lex_less(dv, iv, pd, pi2);      \
                    if (seg == 0 && ct) { ld = cp2 ? pd : dv; li = cp2 ? pi2 : iv; } \
                }                                                               \
            }                                                                   \
            if (__popc(m1) >= MTHR) {                                           \
                merge16(d2b, (CI), ld, li, lane, 1);                            \
            } else {                                                            \
                while (m1) {                                                    \
                    const int src = __ffs(m1) - 1;                              \
                    m1 &= m1 - 1;                                               \
                    const float dv = __shfl_sync(FULL, d2b, src);               \
                    const int   iv = __shfl_sync(FULL, (CI), src);              \
                    const float pd = __shfl_up_sync(FULL, ld, 1, 16);           \
                    const int   pi2 = __shfl_up_sync(FULL, li, 1, 16);          \
                    const bool ct = lex_less(dv, iv, ld, li);                   \
                    const bool cp2 = (t > 0) && lex_less(dv, iv, pd, pi2);      \
                    if (seg == 1 && ct) { ld = cp2 ? pd : dv; li = cp2 ? pi2 : iv; } \
                }                                                               \
            }                                                                   \
            if (had0) tau0 = __shfl_sync(FULL, ld, 15);                         \
            if (had1) tau1 = __shfl_sync(FULL, ld, 31);                         \
        }                                                                       \
    }

#define WARMUP(CC, CI)                                                          \
    {                                                                           \
        float dot0 = q0x * (CC).x;                                              \
        dot0 = fmaf(q0y, (CC).y, dot0);                                         \
        dot0 = fmaf(q0z, (CC).z, dot0);                                         \
        float dot1 = q1x * (CC).x;                                              \
        dot1 = fmaf(q1y, (CC).y, dot1);                                         \
        dot1 = fmaf(q1z, (CC).z, dot1);                                         \
        const float d2a = fmaf(-2.0f, dot0, sq0 + (CC).w);                      \
        const float d2b = fmaf(-2.0f, dot1, sq1 + (CC).w);                      \
        float da = d2a; int ia = (CI);                                          \
        bitonic32(da, ia, lane);                                                \
        float db = d2b; int ib = (CI);                                          \
        bitonic32(db, ib, lane);                                                \
        const float d1v = __shfl_sync(FULL, db, (lane - 16) & 31);              \
        const int   i1v = __shfl_sync(FULL, ib, (lane - 16) & 31);              \
        ld = seg ? d1v : da;                                                    \
        li = seg ? i1v : ia;                                                    \
        tau0 = __shfl_sync(FULL, ld, 15);                                       \
        tau1 = __shfl_sync(FULL, ld, 31);                                       \
    }

#define DORANGE(PS, PE)                                                         \
    {                                                                           \
        int p0 = (PS);                                                          \
        if (!warm && p0 < (PE)) {                                               \
            const int pp = p0 + lane;                                           \
            const bool ok = pp < (PE);                                          \
            const float4 cw = ok ? zp[pp] : make_float4(0.f, 0.f, 0.f, FLT_MAX); \
            const int   cwi = ok ? zi[pp] : 0x7fffffff;                         \
            WARMUP(cw, cwi);                                                    \
            warm = true;                                                        \
            p0 += 32;                                                           \
        }                                                                       \
        if (p0 < (PE)) {                                                        \
            int pp = p0 + lane;                                                 \
            bool ok = pp < (PE);                                                \
            float4 cc = ok ? zp[pp] : make_float4(0.f, 0.f, 0.f, FLT_MAX);      \
            int    ci = ok ? zi[pp] : 0x7fffffff;                               \
            for (; p0 < (PE); p0 += 32) {                                       \
                float4 nc = make_float4(0.f, 0.f, 0.f, FLT_MAX);                \
                int    ni = 0x7fffffff;                                         \
                if (p0 + 32 < (PE)) {                                           \
                    const int np2 = p0 + 32 + lane;                             \
                    const bool nok = np2 < (PE);                                \
                    if (nok) { nc = zp[np2]; ni = zi[np2]; }                    \
                }                                                               \
                ROUND(cc, ci);                                                  \
                cc = nc; ci = ni;                                               \
            }                                                                   \
        }                                                                       \
    }

    // Current tau-certified y-bin window (union over both queries).
#define YWIN(YLO, YHI)                                                          \
    {                                                                           \
        if (warm && tau0 < FLT_MAX && tau1 < FLT_MAX) {                         \
            const float r0 = sqrtf(tau0) * 1.001f;                              \
            const float r1 = sqrtf(tau1) * 1.001f;                              \
            (YLO) = min(biny(q0y - r0, ymn, invy), biny(q1y - r1, ymn, invy));  \
            (YHI) = max(biny(q0y + r0, ymn, invy), biny(q1y + r1, ymn, invy));  \
        } else { (YLO) = 0; (YHI) = NBY - 1; }                                  \
    }

    // ---- Seed: bins [yb-2, yb+2] of the home slab (closest candidates first) ----
    const int sl = max(0, yb - 2), sh = min(NBY - 1, yb + 2);
    DORANGE(bst[h * NBY + sl], bst[h * NBY + sh + 1]);

    // ---- Home-slab remainder under the seeded window ----
    {
        int ylo, yhi;
        YWIN(ylo, yhi);
        if (ylo < sl) DORANGE(bst[h * NBY + ylo], bst[h * NBY + sl]);
        if (yhi > sh) DORANGE(bst[h * NBY + sh + 1], bst[h * NBY + yhi + 1]);
    }

    // ---- Outward slab walk with per-slab y-windows ----
    int lo = h, hi = h;
    for (;;) {
        float bd0 = FLT_MAX, bd1 = FLT_MAX;
        if (lo > 0) {
            const float e = zmn + lo * wz;
            bd0 = fminf(bd0, q0z - e);
            bd1 = fminf(bd1, q1z - e);
        }
        if (hi < NBZ - 1) {
            const float e = zmn + (hi + 1) * wz;
            bd0 = fminf(bd0, e - q0z);
            bd1 = fminf(bd1, e - q1z);
        }
        const bool cov = (lo == 0) && (hi == NBZ - 1);
        const bool d0 = (tau0 < FLT_MAX) && (bd0 > 0.0f) && (tau0 <= 0.98f * bd0 * bd0);
        const bool d1 = (tau1 < FLT_MAX) && (bd1 > 0.0f) && (tau1 <= 0.98f * bd1 * bd1);
        if (cov || (d0 && d1)) break;

        bool up;
        if (lo == 0) up = true;
        else if (hi == NBZ - 1) up = false;
        else {
            const float zm = 0.5f * (q0z + q1z);
            const float du = (zmn + (hi + 1) * wz) - zm;
            const float dd = zm - (zmn + lo * wz);
            up = du <= dd;
        }
        int s2 = up ? ++hi : --lo;
        int ylo, yhi;
        YWIN(ylo, yhi);
        DORANGE(bst[s2 * NBY + ylo], bst[s2 * NBY + yhi + 1]);
    }
#undef ROUND
#undef WARMUP
#undef DORANGE
#undef YWIN

    // ---- Epilogue: features [B,N,K,10] then indices [B,N,K] as float ----
    const float* __restrict__ bx = xyz + (size_t)b * NN * 3;
    const size_t feat_total = (size_t)BB * NN * KK * 10;
    const bool write_idx = ((size_t)out_size >= feat_total + (size_t)BB * NN * KK);
    {
        const int   q  = seg ? qid1 : qid0;
        const float qx = seg ? q1x : q0x;
        const float qy = seg ? q1y : q0y;
        const float qz = seg ? q1z : q0z;
        const size_t qlin = (size_t)b * NN + q;
        const int j = li;
        const float nx = bx[3 * j + 0];
        const float ny = bx[3 * j + 1];
        const float nz = bx[3 * j + 2];

        float* o = out + qlin * KK * 10 + (size_t)t * 10;
        o[0] = ld;
        o[1] = qx - nx;
        o[2] = qy - ny;
        o[3] = qz - nz;
        o[4] = qx;
        o[5] = qy;
        o[6] = qz;
        o[7] = nx;
        o[8] = ny;
        o[9] = nz;
        if (write_idx) out[feat_total + qlin * KK + t] = (float)j;
    }
}

extern "C" void kernel_launch(void* const* d_in, const int* in_sizes, int n_in,
                              void* d_out, int out_size) {
    const float* xyz = (const float*)d_in[0];
    float* out = (float*)d_out;

    k_build<<<BB, 1024>>>(xyz);                              // launch 1
    k_search<<<BB * BPB, TPB>>>(xyz, out, out_size);         // launch 2
}